// round 11
// baseline (speedup 1.0000x reference)
#include <cuda_runtime.h>
#include <cuda_fp16.h>
#include <stdint.h>

#define N_NODES 100000
#define IN_F    512
#define OUT_F   512
#define N_EDGES 3200000
#define M_PAD   100096   // 782 * 128

// ================= device scratch (no runtime allocation) =================
__device__ __half g_support[(size_t)M_PAD * OUT_F];   // fp16 support
__device__ __half g_A_hi[(size_t)M_PAD * IN_F];
__device__ __half g_Wt[(size_t)OUT_F * IN_F];         // [n][k] = W[k][n], fp16
__device__ int   g_row_ptr[N_NODES + 1];
__device__ int   g_cursor[N_NODES];
__device__ unsigned long long g_edge_sorted[N_EDGES]; // (val_bits<<32)|col
__device__ int   g_blk_sums[128];

// ================= HMMA GEMM decls needed by ctor =================
#define BK        32
#define ROW_H     40                      // halves per smem row (80 B)
#define TILE_B    (128 * ROW_H * 2)       // 10240 B per tile
#define STAGE_B   (2 * TILE_B)            // A + W = 20480 B
#define N_STAGE   3
#define SMEM_TOT  (N_STAGE * STAGE_B)     // 61440 B
#define N_CHUNK   (IN_F / BK)             // 16

__global__ void k_gemm_mma(int ntile_base);

// ===== streams/events for fork-join inside graph capture (created once,
// before harness memory checkpoints; not device-memory allocation) =====
namespace {
struct Ctx {
    cudaStream_t side;
    cudaEvent_t  e_fork, e_g0, e_g1, e_g2, e_s2;
    Ctx() {
        cudaStreamCreateWithFlags(&side, cudaStreamNonBlocking);
        cudaEventCreateWithFlags(&e_fork, cudaEventDisableTiming);
        cudaEventCreateWithFlags(&e_g0,   cudaEventDisableTiming);
        cudaEventCreateWithFlags(&e_g1,   cudaEventDisableTiming);
        cudaEventCreateWithFlags(&e_g2,   cudaEventDisableTiming);
        cudaEventCreateWithFlags(&e_s2,   cudaEventDisableTiming);
        cudaFuncSetAttribute(k_gemm_mma,
                             cudaFuncAttributeMaxDynamicSharedMemorySize, SMEM_TOT);
    }
};
Ctx g_ctx;
}

// ================= prep =================
__global__ void k_prep_W(const float* __restrict__ weight) {
    int i = blockIdx.x * blockDim.x + threadIdx.x;   // 0..262143
    int n = i >> 9, k = i & 511;
    g_Wt[i] = __float2half_rn(weight[(size_t)k * OUT_F + n]);
}
__global__ void k_split_A(const float* __restrict__ features) {
    long long t = (long long)blockIdx.x * blockDim.x + threadIdx.x;  // one float4 each
    const long long total = (long long)M_PAD * IN_F / 4;
    if (t >= total) return;
    int row = (int)(t >> 7);
    int q   = (int)(t & 127);
    float4 v = make_float4(0.f, 0.f, 0.f, 0.f);
    if (row < N_NODES)
        v = *reinterpret_cast<const float4*>(&features[(size_t)row * IN_F + q * 4]);
    union { uint2 u; __half h[4]; } H;
    H.h[0] = __float2half_rn(v.x);
    H.h[1] = __float2half_rn(v.y);
    H.h[2] = __float2half_rn(v.z);
    H.h[3] = __float2half_rn(v.w);
    *reinterpret_cast<uint2*>(&g_A_hi[(size_t)row * IN_F + q * 4]) = H.u;
}

// ================= CSR build =================
__global__ void k_zero_counts() {
    int i = blockIdx.x * blockDim.x + threadIdx.x;
    if (i < N_NODES) g_cursor[i] = 0;
}
__global__ void k_hist(const int* __restrict__ edge_row) {
    int e = blockIdx.x * blockDim.x + threadIdx.x;
    if (e < N_EDGES) atomicAdd(&g_cursor[edge_row[e]], 1);
}
__global__ void k_scan1() {
    __shared__ int s[1024];
    int i = blockIdx.x * 1024 + threadIdx.x;
    int v = (i < N_NODES) ? g_cursor[i] : 0;
    s[threadIdx.x] = v;
    __syncthreads();
    #pragma unroll
    for (int d = 1; d < 1024; d <<= 1) {
        int t = (threadIdx.x >= (unsigned)d) ? s[threadIdx.x - d] : 0;
        __syncthreads();
        s[threadIdx.x] += t;
        __syncthreads();
    }
    if (i < N_NODES) g_row_ptr[i] = s[threadIdx.x] - v;   // block-local exclusive
    if (threadIdx.x == 1023) g_blk_sums[blockIdx.x] = s[1023];
}
// scan of 98 block sums, redundant per block in smem, then applied
__global__ void k_scan23() {
    __shared__ int s[128];
    if (threadIdx.x < 128) {
        int v = (threadIdx.x < 98) ? g_blk_sums[threadIdx.x] : 0;
        s[threadIdx.x] = v;
        __syncthreads();
        #pragma unroll
        for (int d = 1; d < 128; d <<= 1) {
            int t = (threadIdx.x >= (unsigned)d) ? s[threadIdx.x - d] : 0;
            __syncthreads();
            s[threadIdx.x] += t;
            __syncthreads();
        }
    } else {
        __syncthreads();
        #pragma unroll
        for (int d = 1; d < 128; d <<= 1) { __syncthreads(); __syncthreads(); }
    }
    __syncthreads();
    int i = blockIdx.x * blockDim.x + threadIdx.x;
    if (i < N_NODES) {
        int blk = i >> 10;
        int base = (blk == 0) ? 0 : s[blk - 1];     // exclusive
        int e = g_row_ptr[i] + base;
        g_row_ptr[i] = e;
        g_cursor[i]  = e;
    }
    if (i == 0) g_row_ptr[N_NODES] = s[97];
}
__global__ void k_scatter(const int* __restrict__ edge_row,
                          const int* __restrict__ edge_col,
                          const float* __restrict__ edge_val) {
    int e = blockIdx.x * blockDim.x + threadIdx.x;
    if (e < N_EDGES) {
        int r = edge_row[e];
        int p = atomicAdd(&g_cursor[r], 1);
        unsigned long long pk =
            ((unsigned long long)__float_as_uint(edge_val[e]) << 32)
            | (unsigned)edge_col[e];
        g_edge_sorted[p] = pk;
    }
}

// ================= HMMA GEMM: support = A @ W, fp32 accum =================
// BM=128, BN=128, BK=32, 256 threads (8 warps: 2 m-halves x 4 n-strips).
// 3-stage cp.async pipeline, one __syncthreads per K-chunk.
// smem rows: 32 data + 8 pad fp16 = 80B stride -> conflict-free ldmatrix.
__device__ __forceinline__ void ldmatrix_x4(uint32_t* r, uint32_t addr) {
    asm volatile("ldmatrix.sync.aligned.m8n8.x4.shared.b16 {%0,%1,%2,%3}, [%4];"
                 : "=r"(r[0]), "=r"(r[1]), "=r"(r[2]), "=r"(r[3]) : "r"(addr));
}
__device__ __forceinline__ void ldmatrix_x2(uint32_t* r, uint32_t addr) {
    asm volatile("ldmatrix.sync.aligned.m8n8.x2.shared.b16 {%0,%1}, [%2];"
                 : "=r"(r[0]), "=r"(r[1]) : "r"(addr));
}
__device__ __forceinline__ void mma16816(float* d, const uint32_t* a, const uint32_t* b) {
    asm volatile(
        "mma.sync.aligned.m16n8k16.row.col.f32.f16.f16.f32 "
        "{%0,%1,%2,%3}, {%4,%5,%6,%7}, {%8,%9}, {%0,%1,%2,%3};"
        : "+f"(d[0]), "+f"(d[1]), "+f"(d[2]), "+f"(d[3])
        : "r"(a[0]), "r"(a[1]), "r"(a[2]), "r"(a[3]), "r"(b[0]), "r"(b[1]));
}
__device__ __forceinline__ void cp_async16(uint32_t smem_addr, const void* gptr) {
    asm volatile("cp.async.cg.shared.global [%0], [%1], 16;"
                 :: "r"(smem_addr), "l"(gptr));
}
__device__ __forceinline__ void cp_commit() {
    asm volatile("cp.async.commit_group;");
}
template <int N>
__device__ __forceinline__ void cp_wait() {
    asm volatile("cp.async.wait_group %0;" :: "n"(N));
}
__device__ __forceinline__ uint32_t smem_u32(const void* p) {
    uint32_t a;
    asm("{ .reg .u64 t; cvta.to.shared.u64 t, %1; cvt.u32.u64 %0, t; }"
        : "=r"(a) : "l"(p));
    return a;
}

__global__ __launch_bounds__(256, 2) void k_gemm_mma(int ntile_base) {
    extern __shared__ __align__(16) char smem[];

    const int tid  = threadIdx.x;
    const int wid  = tid >> 5;
    const int lane = tid & 31;
    const int wm   = wid & 1;          // 0..1 (64 rows each)
    const int wn   = wid >> 1;         // 0..3 (32 cols each)
    const int mtile = blockIdx.y;
    const int ntile = ntile_base + blockIdx.x;

    const __half* A_h = g_A_hi + (size_t)mtile * 128 * IN_F;
    const __half* B_t = g_Wt   + (size_t)ntile * 128 * IN_F;

    const uint32_t sbase = smem_u32(smem);

    float acc[4][4][4];
    #pragma unroll
    for (int i = 0; i < 4; i++)
        #pragma unroll
        for (int j = 0; j < 4; j++)
            #pragma unroll
            for (int k = 0; k < 4; k++) acc[i][j][k] = 0.f;

    const int a_r  = lane & 15;
    const int a_hi = (lane >> 4) * 16;     // byte offset within 16-half k-step
    const int b_r  = lane & 7;
    const int b_hi = ((lane >> 3) & 1) * 16;

    auto load_stage = [&](int c, int s) {
        const int k0 = c * BK;
        const uint32_t st = sbase + s * STAGE_B;
        #pragma unroll
        for (int it = 0; it < 2; it++) {
            int idx = it * 256 + tid;
            int row = idx >> 2, q = idx & 3;
            uint32_t so = (uint32_t)row * (ROW_H * 2) + q * 16;
            const __half* ga = A_h + (size_t)row * IN_F + k0 + q * 8;
            const __half* gb = B_t + (size_t)row * IN_F + k0 + q * 8;
            cp_async16(st + so,          ga);
            cp_async16(st + TILE_B + so, gb);
        }
        cp_commit();
    };

    load_stage(0, 0);
    load_stage(1, 1);

    for (int c = 0; c < N_CHUNK; c++) {
        if (c == N_CHUNK - 1) cp_wait<0>(); else cp_wait<1>();
        __syncthreads();

        const int s = c % N_STAGE;
        const uint32_t st  = sbase + s * STAGE_B;
        const uint32_t sAH = st;
        const uint32_t sWT = st + TILE_B;

        #pragma unroll
        for (int ks = 0; ks < 2; ks++) {
            uint32_t bfrag[4][2];
            #pragma unroll
            for (int nt = 0; nt < 4; nt++) {
                uint32_t addr = sWT + (uint32_t)(wn * 32 + nt * 8 + b_r) * (ROW_H * 2)
                                + ks * 32 + b_hi;
                ldmatrix_x2(bfrag[nt], addr);
            }
            #pragma unroll
            for (int mt = 0; mt < 4; mt++) {
                uint32_t a[4];
                uint32_t addr = sAH + (uint32_t)(wm * 64 + mt * 16 + a_r) * (ROW_H * 2)
                                + ks * 32 + a_hi;
                ldmatrix_x4(a, addr);
                #pragma unroll
                for (int nt = 0; nt < 4; nt++) mma16816(acc[mt][nt], a, bfrag[nt]);
            }
        }

        if (c + 2 < N_CHUNK) load_stage(c + 2, (c + 2) % N_STAGE);
    }

    // epilogue: fp32 accum -> fp16 support
    const int mbase = mtile * 128 + wm * 64;
    const int nbase = ntile * 128 + wn * 32;
    #pragma unroll
    for (int mt = 0; mt < 4; mt++) {
        int r0 = mbase + mt * 16 + (lane >> 2);
        int col = nbase + 2 * (lane & 3);
        #pragma unroll
        for (int nt = 0; nt < 4; nt++) {
            int cc = col + nt * 8;
            if (r0 < N_NODES) {
                __half2 h = __floats2half2_rn(acc[mt][nt][0], acc[mt][nt][1]);
                *reinterpret_cast<__half2*>(&g_support[(size_t)r0 * OUT_F + cc]) = h;
            }
            if (r0 + 8 < N_NODES) {
                __half2 h = __floats2half2_rn(acc[mt][nt][2], acc[mt][nt][3]);
                *reinterpret_cast<__half2*>(&g_support[(size_t)(r0 + 8) * OUT_F + cc]) = h;
            }
        }
    }
}

// ================= CSR SpMM quarter (128 cols) + ReLU =================
// one warp per row (32 threads x 4 cols = 128 cols), 4 rows per 128-thread block
__global__ __launch_bounds__(128) void k_spmm_q(float* __restrict__ out,
                                                int col_base) {
    const int r = blockIdx.x * 4 + (threadIdx.x >> 5);
    const int t = threadIdx.x & 31;
    if (r >= N_NODES) return;

    const int start = g_row_ptr[r];
    const int end   = g_row_ptr[r + 1];
    const int cb    = col_base + t * 4;

    float a0 = 0.f, a1 = 0.f, a2 = 0.f, a3 = 0.f;

    #pragma unroll 4
    for (int i = start; i < end; i++) {
        unsigned long long pk = __ldg(&g_edge_sorted[i]);
        int   c = (int)(unsigned)pk;
        float v = __uint_as_float((unsigned)(pk >> 32));
        uint2 u = *reinterpret_cast<const uint2*>(
            &g_support[(size_t)c * OUT_F + cb]);
        __half2 h0 = *reinterpret_cast<__half2*>(&u.x);
        __half2 h1 = *reinterpret_cast<__half2*>(&u.y);
        float2 f0 = __half22float2(h0);
        float2 f1 = __half22float2(h1);
        a0 = fmaf(v, f0.x, a0);
        a1 = fmaf(v, f0.y, a1);
        a2 = fmaf(v, f1.x, a2);
        a3 = fmaf(v, f1.y, a3);
    }

    float4 o = make_float4(fmaxf(a0, 0.f), fmaxf(a1, 0.f),
                           fmaxf(a2, 0.f), fmaxf(a3, 0.f));
    *reinterpret_cast<float4*>(&out[(size_t)r * OUT_F + cb]) = o;
}

// ================= launch =================
// 4-stage column pipeline: main stream runs prep + G0..G3; side stream runs
// CSR then S0..S2 each gated on its GEMM quarter; main waits e_s2 (terminal
// join, implies CSR done) then runs S3.
extern "C" void kernel_launch(void* const* d_in, const int* in_sizes, int n_in,
                              void* d_out, int out_size) {
    const float* features = (const float*)d_in[0];
    const float* weight   = (const float*)d_in[1];
    const int*   edge_row = (const int*)d_in[2];
    const int*   edge_col = (const int*)d_in[3];
    const float* edge_val = (const float*)d_in[4];
    float*       out      = (float*)d_out;

    // fork
    cudaEventRecord(g_ctx.e_fork, 0);
    cudaStreamWaitEvent(g_ctx.side, g_ctx.e_fork, 0);

    // ---- side stream: CSR build ----
    k_zero_counts<<<(N_NODES + 255) / 256, 256, 0, g_ctx.side>>>();
    k_hist<<<(N_EDGES + 255) / 256, 256, 0, g_ctx.side>>>(edge_row);
    k_scan1<<<98, 1024, 0, g_ctx.side>>>();
    k_scan23<<<(N_NODES + 255) / 256, 256, 0, g_ctx.side>>>();
    k_scatter<<<(N_EDGES + 255) / 256, 256, 0, g_ctx.side>>>(edge_row, edge_col,
                                                             edge_val);

    // ---- main stream: fp16 prep + GEMM quarters ----
    k_prep_W<<<(OUT_F * IN_F) / 256, 256>>>(weight);
    {
        long long total = (long long)M_PAD * IN_F / 4;
        k_split_A<<<(unsigned)((total + 255) / 256), 256>>>(features);
    }
    k_gemm_mma<<<dim3(1, M_PAD / 128), 256, SMEM_TOT>>>(0);
    cudaEventRecord(g_ctx.e_g0, 0);
    k_gemm_mma<<<dim3(1, M_PAD / 128), 256, SMEM_TOT>>>(1);
    cudaEventRecord(g_ctx.e_g1, 0);
    k_gemm_mma<<<dim3(1, M_PAD / 128), 256, SMEM_TOT>>>(2);
    cudaEventRecord(g_ctx.e_g2, 0);
    k_gemm_mma<<<dim3(1, M_PAD / 128), 256, SMEM_TOT>>>(3);

    // ---- side stream: SpMM quarters 0..2, each after its GEMM quarter ----
    cudaStreamWaitEvent(g_ctx.side, g_ctx.e_g0, 0);
    k_spmm_q<<<N_NODES / 4, 128, 0, g_ctx.side>>>(out, 0);
    cudaStreamWaitEvent(g_ctx.side, g_ctx.e_g1, 0);
    k_spmm_q<<<N_NODES / 4, 128, 0, g_ctx.side>>>(out, 128);
    cudaStreamWaitEvent(g_ctx.side, g_ctx.e_g2, 0);
    k_spmm_q<<<N_NODES / 4, 128, 0, g_ctx.side>>>(out, 256);
    cudaEventRecord(g_ctx.e_s2, g_ctx.side);

    // ---- main stream: join side, final SpMM quarter ----
    cudaStreamWaitEvent(0, g_ctx.e_s2, 0);
    k_spmm_q<<<N_NODES / 4, 128>>>(out, 384);
}

// round 12
// speedup vs baseline: 1.0677x; 1.0677x over previous
#include <cuda_runtime.h>
#include <cuda_fp16.h>
#include <stdint.h>

#define N_NODES 100000
#define IN_F    512
#define OUT_F   512
#define N_EDGES 3200000
#define M_PAD   100096   // 782 * 128

// ================= device scratch (no runtime allocation) =================
__device__ __half g_support[(size_t)M_PAD * OUT_F];   // fp16 support
__device__ __half g_Wt[(size_t)OUT_F * IN_F];         // [n][k] = W[k][n], fp16
__device__ int   g_row_ptr[N_NODES + 1];
__device__ int   g_cursor[N_NODES];
__device__ unsigned long long g_edge_sorted[N_EDGES]; // (val_bits<<32)|col
__device__ int   g_blk_sums[128];

// ================= HMMA GEMM decls needed by ctor =================
#define BK        32
#define ROW_H     40                      // halves per smem row (80 B)
#define TILE_B    (128 * ROW_H * 2)       // 10240 B per tile
#define STAGE_B   (2 * TILE_B)            // A + W = 20480 B
#define N_STAGE   3
#define SMEM_TOT  (N_STAGE * STAGE_B)     // 61440 B
#define N_CHUNK   (IN_F / BK)             // 16

__global__ void k_gemm_mma(const float* __restrict__ A, int ntile_base);

// ===== streams/events for fork-join inside graph capture (created once,
// before harness memory checkpoints; not device-memory allocation) =====
namespace {
struct Ctx {
    cudaStream_t side;
    cudaEvent_t  e_fork, e_g0, e_s0;
    Ctx() {
        cudaStreamCreateWithFlags(&side, cudaStreamNonBlocking);
        cudaEventCreateWithFlags(&e_fork, cudaEventDisableTiming);
        cudaEventCreateWithFlags(&e_g0,   cudaEventDisableTiming);
        cudaEventCreateWithFlags(&e_s0,   cudaEventDisableTiming);
        cudaFuncSetAttribute(k_gemm_mma,
                             cudaFuncAttributeMaxDynamicSharedMemorySize, SMEM_TOT);
    }
};
Ctx g_ctx;
}

// ================= prep: W transpose -> fp16 =================
__global__ void k_prep_W(const float* __restrict__ weight) {
    int i = blockIdx.x * blockDim.x + threadIdx.x;   // 0..262143
    int n = i >> 9, k = i & 511;
    g_Wt[i] = __float2half_rn(weight[(size_t)k * OUT_F + n]);
}

// ================= CSR build =================
__global__ void k_zero_counts() {
    int i = blockIdx.x * blockDim.x + threadIdx.x;
    if (i < N_NODES) g_cursor[i] = 0;
}
__global__ void k_hist(const int* __restrict__ edge_row) {
    int e = blockIdx.x * blockDim.x + threadIdx.x;
    if (e < N_EDGES) atomicAdd(&g_cursor[edge_row[e]], 1);
}
__global__ void k_scan1() {
    __shared__ int s[1024];
    int i = blockIdx.x * 1024 + threadIdx.x;
    int v = (i < N_NODES) ? g_cursor[i] : 0;
    s[threadIdx.x] = v;
    __syncthreads();
    #pragma unroll
    for (int d = 1; d < 1024; d <<= 1) {
        int t = (threadIdx.x >= (unsigned)d) ? s[threadIdx.x - d] : 0;
        __syncthreads();
        s[threadIdx.x] += t;
        __syncthreads();
    }
    if (i < N_NODES) g_row_ptr[i] = s[threadIdx.x] - v;   // block-local exclusive
    if (threadIdx.x == 1023) g_blk_sums[blockIdx.x] = s[1023];
}
// scan of 98 block sums, redundant per block in smem, then applied
__global__ void k_scan23() {
    __shared__ int s[128];
    if (threadIdx.x < 128) {
        int v = (threadIdx.x < 98) ? g_blk_sums[threadIdx.x] : 0;
        s[threadIdx.x] = v;
        __syncthreads();
        #pragma unroll
        for (int d = 1; d < 128; d <<= 1) {
            int t = (threadIdx.x >= (unsigned)d) ? s[threadIdx.x - d] : 0;
            __syncthreads();
            s[threadIdx.x] += t;
            __syncthreads();
        }
    } else {
        __syncthreads();
        #pragma unroll
        for (int d = 1; d < 128; d <<= 1) { __syncthreads(); __syncthreads(); }
    }
    __syncthreads();
    int i = blockIdx.x * blockDim.x + threadIdx.x;
    if (i < N_NODES) {
        int blk = i >> 10;
        int base = (blk == 0) ? 0 : s[blk - 1];     // exclusive
        int e = g_row_ptr[i] + base;
        g_row_ptr[i] = e;
        g_cursor[i]  = e;
    }
    if (i == 0) g_row_ptr[N_NODES] = s[97];
}
__global__ void k_scatter(const int* __restrict__ edge_row,
                          const int* __restrict__ edge_col,
                          const float* __restrict__ edge_val) {
    int e = blockIdx.x * blockDim.x + threadIdx.x;
    if (e < N_EDGES) {
        int r = edge_row[e];
        int p = atomicAdd(&g_cursor[r], 1);
        unsigned long long pk =
            ((unsigned long long)__float_as_uint(edge_val[e]) << 32)
            | (unsigned)edge_col[e];
        g_edge_sorted[p] = pk;
    }
}

// ================= HMMA GEMM: support = A(fp32, inline-converted) @ W ========
// BM=128, BN=128, BK=32, 256 threads (8 warps: 2 m-halves x 4 n-strips).
// A: fp32 LDG register-prefetch one chunk ahead, converted to fp16 + STS.
// W: 3-stage cp.async pipeline. One __syncthreads per K-chunk.
// smem rows: 32 data + 8 pad fp16 = 80B stride -> conflict-free ldmatrix.
__device__ __forceinline__ void ldmatrix_x4(uint32_t* r, uint32_t addr) {
    asm volatile("ldmatrix.sync.aligned.m8n8.x4.shared.b16 {%0,%1,%2,%3}, [%4];"
                 : "=r"(r[0]), "=r"(r[1]), "=r"(r[2]), "=r"(r[3]) : "r"(addr));
}
__device__ __forceinline__ void ldmatrix_x2(uint32_t* r, uint32_t addr) {
    asm volatile("ldmatrix.sync.aligned.m8n8.x2.shared.b16 {%0,%1}, [%2];"
                 : "=r"(r[0]), "=r"(r[1]) : "r"(addr));
}
__device__ __forceinline__ void mma16816(float* d, const uint32_t* a, const uint32_t* b) {
    asm volatile(
        "mma.sync.aligned.m16n8k16.row.col.f32.f16.f16.f32 "
        "{%0,%1,%2,%3}, {%4,%5,%6,%7}, {%8,%9}, {%0,%1,%2,%3};"
        : "+f"(d[0]), "+f"(d[1]), "+f"(d[2]), "+f"(d[3])
        : "r"(a[0]), "r"(a[1]), "r"(a[2]), "r"(a[3]), "r"(b[0]), "r"(b[1]));
}
__device__ __forceinline__ void cp_async16(uint32_t smem_addr, const void* gptr) {
    asm volatile("cp.async.cg.shared.global [%0], [%1], 16;"
                 :: "r"(smem_addr), "l"(gptr));
}
__device__ __forceinline__ void cp_commit() {
    asm volatile("cp.async.commit_group;");
}
template <int N>
__device__ __forceinline__ void cp_wait() {
    asm volatile("cp.async.wait_group %0;" :: "n"(N));
}
__device__ __forceinline__ uint32_t smem_u32(const void* p) {
    uint32_t a;
    asm("{ .reg .u64 t; cvta.to.shared.u64 t, %1; cvt.u32.u64 %0, t; }"
        : "=r"(a) : "l"(p));
    return a;
}

__global__ __launch_bounds__(256, 2) void k_gemm_mma(const float* __restrict__ A,
                                                     int ntile_base) {
    extern __shared__ __align__(16) char smem[];

    const int tid  = threadIdx.x;
    const int wid  = tid >> 5;
    const int lane = tid & 31;
    const int wm   = wid & 1;          // 0..1 (64 rows each)
    const int wn   = wid >> 1;         // 0..3 (32 cols each)
    const int mtile = blockIdx.y;
    const int ntile = ntile_base + blockIdx.x;

    const __half* B_t = g_Wt + (size_t)ntile * 128 * IN_F;
    const uint32_t sbase = smem_u32(smem);

    // --- A fp32 register prefetch mapping: 2 threads/row, 16 floats each ---
    const int arow = tid >> 1;                 // 0..127
    const int aq   = tid & 1;                  // col group: aq*16
    const int grow = mtile * 128 + arow;
    const bool aval = (grow < N_NODES);
    const float* agp = A + (size_t)grow * IN_F + aq * 16;
    const uint32_t a_sts = (uint32_t)arow * (ROW_H * 2) + aq * 32;

    float4 ar[4];
    auto load_A = [&](int c) {
        if (aval) {
            const float* p = agp + c * BK;
            ar[0] = *reinterpret_cast<const float4*>(p);
            ar[1] = *reinterpret_cast<const float4*>(p + 4);
            ar[2] = *reinterpret_cast<const float4*>(p + 8);
            ar[3] = *reinterpret_cast<const float4*>(p + 12);
        } else {
            ar[0] = ar[1] = ar[2] = ar[3] = make_float4(0.f, 0.f, 0.f, 0.f);
        }
    };
    auto store_A = [&](int s) {
        union { __half2 h2[8]; uint4 u4[2]; } U;
        U.h2[0] = __floats2half2_rn(ar[0].x, ar[0].y);
        U.h2[1] = __floats2half2_rn(ar[0].z, ar[0].w);
        U.h2[2] = __floats2half2_rn(ar[1].x, ar[1].y);
        U.h2[3] = __floats2half2_rn(ar[1].z, ar[1].w);
        U.h2[4] = __floats2half2_rn(ar[2].x, ar[2].y);
        U.h2[5] = __floats2half2_rn(ar[2].z, ar[2].w);
        U.h2[6] = __floats2half2_rn(ar[3].x, ar[3].y);
        U.h2[7] = __floats2half2_rn(ar[3].z, ar[3].w);
        uint4* dst = reinterpret_cast<uint4*>(smem + s * STAGE_B + a_sts);
        dst[0] = U.u4[0];
        dst[1] = U.u4[1];
    };
    // --- W cp.async: 512 16B chunks per tile, 2 per thread ---
    const int wrow0 = tid >> 2, wq0 = tid & 3;            // idx = tid
    const int wrow1 = (256 + tid) >> 2, wq1 = (256 + tid) & 3; // idx = 256+tid
    auto load_W = [&](int c, int s) {
        const int k0 = c * BK;
        const uint32_t st = sbase + s * STAGE_B + TILE_B;
        cp_async16(st + (uint32_t)wrow0 * (ROW_H * 2) + wq0 * 16,
                   B_t + (size_t)wrow0 * IN_F + k0 + wq0 * 8);
        cp_async16(st + (uint32_t)wrow1 * (ROW_H * 2) + wq1 * 16,
                   B_t + (size_t)wrow1 * IN_F + k0 + wq1 * 8);
        cp_commit();
    };

    float acc[4][4][4];
    #pragma unroll
    for (int i = 0; i < 4; i++)
        #pragma unroll
        for (int j = 0; j < 4; j++)
            #pragma unroll
            for (int k = 0; k < 4; k++) acc[i][j][k] = 0.f;

    const int a_r  = lane & 15;
    const int a_hi = (lane >> 4) * 16;     // byte offset within 16-half k-step
    const int b_r  = lane & 7;
    const int b_hi = ((lane >> 3) & 1) * 16;

    // prologue
    load_A(0);
    load_W(0, 0);
    store_A(0);            // stalls on chunk-0 LDG; prologue only
    load_A(1);
    load_W(1, 1);

    for (int c = 0; c < N_CHUNK; c++) {
        if (c == N_CHUNK - 1) cp_wait<0>(); else cp_wait<1>();
        __syncthreads();

        const int s = c % N_STAGE;
        const uint32_t st  = sbase + s * STAGE_B;
        const uint32_t sAH = st;
        const uint32_t sWT = st + TILE_B;

        #pragma unroll
        for (int ks = 0; ks < 2; ks++) {
            uint32_t bfrag[4][2];
            #pragma unroll
            for (int nt = 0; nt < 4; nt++) {
                uint32_t addr = sWT + (uint32_t)(wn * 32 + nt * 8 + b_r) * (ROW_H * 2)
                                + ks * 32 + b_hi;
                ldmatrix_x2(bfrag[nt], addr);
            }
            #pragma unroll
            for (int mt = 0; mt < 4; mt++) {
                uint32_t a[4];
                uint32_t addr = sAH + (uint32_t)(wm * 64 + mt * 16 + a_r) * (ROW_H * 2)
                                + ks * 32 + a_hi;
                ldmatrix_x4(a, addr);
                #pragma unroll
                for (int nt = 0; nt < 4; nt++) mma16816(acc[mt][nt], a, bfrag[nt]);
            }
        }

        // stage A for chunk c+1 (regs loaded last iter), refill regs for c+2
        if (c + 1 < N_CHUNK) store_A((c + 1) % N_STAGE);
        if (c + 2 < N_CHUNK) { load_A(c + 2); load_W(c + 2, (c + 2) % N_STAGE); }
    }

    // epilogue: fp32 accum -> fp16 support
    const int mbase = mtile * 128 + wm * 64;
    const int nbase = ntile * 128 + wn * 32;
    #pragma unroll
    for (int mt = 0; mt < 4; mt++) {
        int r0 = mbase + mt * 16 + (lane >> 2);
        int col = nbase + 2 * (lane & 3);
        #pragma unroll
        for (int nt = 0; nt < 4; nt++) {
            int cc = col + nt * 8;
            if (r0 < N_NODES) {
                __half2 h = __floats2half2_rn(acc[mt][nt][0], acc[mt][nt][1]);
                *reinterpret_cast<__half2*>(&g_support[(size_t)r0 * OUT_F + cc]) = h;
            }
            if (r0 + 8 < N_NODES) {
                __half2 h = __floats2half2_rn(acc[mt][nt][2], acc[mt][nt][3]);
                *reinterpret_cast<__half2*>(&g_support[(size_t)(r0 + 8) * OUT_F + cc]) = h;
            }
        }
    }
}

// ================= CSR SpMM half (256 cols) + ReLU =================
// one warp per row (32 threads x 8 cols = 256 cols), 4 rows per 128-thread block
__global__ __launch_bounds__(128) void k_spmm_half(float* __restrict__ out,
                                                   int col_base) {
    const int r = blockIdx.x * 4 + (threadIdx.x >> 5);
    const int t = threadIdx.x & 31;
    if (r >= N_NODES) return;

    const int start = g_row_ptr[r];
    const int end   = g_row_ptr[r + 1];
    const int cb    = col_base + t * 8;

    float acc[8];
    #pragma unroll
    for (int j = 0; j < 8; j++) acc[j] = 0.f;

    #pragma unroll 4
    for (int i = start; i < end; i++) {
        unsigned long long pk = __ldg(&g_edge_sorted[i]);
        int   c = (int)(unsigned)pk;
        float v = __uint_as_float((unsigned)(pk >> 32));
        uint4 u = *reinterpret_cast<const uint4*>(
            &g_support[(size_t)c * OUT_F + cb]);
        const __half2* h = reinterpret_cast<const __half2*>(&u);
        #pragma unroll
        for (int j = 0; j < 4; j++) {
            float2 f = __half22float2(h[j]);
            acc[2 * j]     = fmaf(v, f.x, acc[2 * j]);
            acc[2 * j + 1] = fmaf(v, f.y, acc[2 * j + 1]);
        }
    }

    float* dst = &out[(size_t)r * OUT_F + cb];
    float4 o0 = make_float4(fmaxf(acc[0], 0.f), fmaxf(acc[1], 0.f),
                            fmaxf(acc[2], 0.f), fmaxf(acc[3], 0.f));
    float4 o1 = make_float4(fmaxf(acc[4], 0.f), fmaxf(acc[5], 0.f),
                            fmaxf(acc[6], 0.f), fmaxf(acc[7], 0.f));
    *reinterpret_cast<float4*>(dst)     = o0;
    *reinterpret_cast<float4*>(dst + 4) = o1;
}

// ================= launch =================
// R10 topology (proven best): side stream runs CSR then SpMM-half0 as soon as
// GEMM-half0 finishes, concurrent with GEMM-half1 on the main stream.
// The terminal e_s0 wait joins the side stream back into the capture.
extern "C" void kernel_launch(void* const* d_in, const int* in_sizes, int n_in,
                              void* d_out, int out_size) {
    const float* features = (const float*)d_in[0];
    const float* weight   = (const float*)d_in[1];
    const int*   edge_row = (const int*)d_in[2];
    const int*   edge_col = (const int*)d_in[3];
    const float* edge_val = (const float*)d_in[4];
    float*       out      = (float*)d_out;

    // fork
    cudaEventRecord(g_ctx.e_fork, 0);
    cudaStreamWaitEvent(g_ctx.side, g_ctx.e_fork, 0);

    // ---- side stream: CSR build ----
    k_zero_counts<<<(N_NODES + 255) / 256, 256, 0, g_ctx.side>>>();
    k_hist<<<(N_EDGES + 255) / 256, 256, 0, g_ctx.side>>>(edge_row);
    k_scan1<<<98, 1024, 0, g_ctx.side>>>();
    k_scan23<<<(N_NODES + 255) / 256, 256, 0, g_ctx.side>>>();
    k_scatter<<<(N_EDGES + 255) / 256, 256, 0, g_ctx.side>>>(edge_row, edge_col,
                                                             edge_val);

    // ---- main stream: W prep + GEMM half 0 (cols 0-255), A converted inline ----
    k_prep_W<<<(OUT_F * IN_F) / 256, 256>>>(weight);
    k_gemm_mma<<<dim3(2, M_PAD / 128), 256, SMEM_TOT>>>(features, 0);
    cudaEventRecord(g_ctx.e_g0, 0);

    // ---- side stream: SpMM half 0 (after its CSR chain + GEMM half 0) ----
    cudaStreamWaitEvent(g_ctx.side, g_ctx.e_g0, 0);
    k_spmm_half<<<N_NODES / 4, 128, 0, g_ctx.side>>>(out, 0);
    cudaEventRecord(g_ctx.e_s0, g_ctx.side);

    // ---- main stream: GEMM half 1 (cols 256-511), then SpMM half 1 ----
    k_gemm_mma<<<dim3(2, M_PAD / 128), 256, SMEM_TOT>>>(features, 2);
    k_spmm_half<<<N_NODES / 4, 128>>>(out, 256);

    // join side stream into the capture (terminal merge)
    cudaStreamWaitEvent(0, g_ctx.e_s0, 0);
}

// round 13
// speedup vs baseline: 1.1169x; 1.0461x over previous
#include <cuda_runtime.h>
#include <cuda_fp16.h>
#include <stdint.h>

#define N_NODES 100000
#define IN_F    512
#define OUT_F   512
#define N_EDGES 3200000
#define M_PAD   100096   // 782 * 128

// ================= device scratch (no runtime allocation) =================
__device__ __half g_support[(size_t)M_PAD * OUT_F];   // fp16 support
__device__ __half g_A_hi[(size_t)M_PAD * IN_F];       // fp16 features
__device__ __half g_Wt[(size_t)OUT_F * IN_F];         // [n][k] = W[k][n], fp16
__device__ int   g_row_ptr[N_NODES + 1];
__device__ int   g_cursor[N_NODES];
__device__ unsigned long long g_edge_sorted[N_EDGES]; // (val_bits<<32)|col
__device__ int   g_blk_sums[128];

// ================= HMMA GEMM decls needed by ctor =================
#define BK        32
#define ROW_H     40                      // halves per smem row (80 B)
#define TILE_B    (128 * ROW_H * 2)       // 10240 B per tile
#define STAGE_B   (2 * TILE_B)            // A + W = 20480 B
#define N_STAGE   3
#define SMEM_TOT  (N_STAGE * STAGE_B)     // 61440 B
#define N_CHUNK   (IN_F / BK)             // 16

__global__ void k_gemm_mma(int ntile_base);

// ===== streams/events for fork-join inside graph capture (created once,
// before harness memory checkpoints; not device-memory allocation) =====
namespace {
struct Ctx {
    cudaStream_t side;
    cudaEvent_t  e_fork, e_w, e_g0, e_s0;
    Ctx() {
        cudaStreamCreateWithFlags(&side, cudaStreamNonBlocking);
        cudaEventCreateWithFlags(&e_fork, cudaEventDisableTiming);
        cudaEventCreateWithFlags(&e_w,    cudaEventDisableTiming);
        cudaEventCreateWithFlags(&e_g0,   cudaEventDisableTiming);
        cudaEventCreateWithFlags(&e_s0,   cudaEventDisableTiming);
        cudaFuncSetAttribute(k_gemm_mma,
                             cudaFuncAttributeMaxDynamicSharedMemorySize, SMEM_TOT);
    }
};
Ctx g_ctx;
}

// ================= prep =================
__global__ void k_prep_W(const float* __restrict__ weight) {
    int i = blockIdx.x * blockDim.x + threadIdx.x;   // 0..262143
    int n = i >> 9, k = i & 511;
    g_Wt[i] = __float2half_rn(weight[(size_t)k * OUT_F + n]);
}
// features -> fp16, 8 floats per thread, one uint4 store
__global__ void k_split_A(const float* __restrict__ features) {
    long long t = (long long)blockIdx.x * blockDim.x + threadIdx.x;
    const long long total = (long long)M_PAD * IN_F / 8;   // 6406144
    if (t >= total) return;
    int row = (int)(t >> 6);          // 64 groups of 8 per row
    int q   = (int)(t & 63);
    float4 v0 = make_float4(0.f, 0.f, 0.f, 0.f);
    float4 v1 = make_float4(0.f, 0.f, 0.f, 0.f);
    if (row < N_NODES) {
        const float* p = &features[(size_t)row * IN_F + q * 8];
        v0 = *reinterpret_cast<const float4*>(p);
        v1 = *reinterpret_cast<const float4*>(p + 4);
    }
    union { uint4 u; __half2 h2[4]; } U;
    U.h2[0] = __floats2half2_rn(v0.x, v0.y);
    U.h2[1] = __floats2half2_rn(v0.z, v0.w);
    U.h2[2] = __floats2half2_rn(v1.x, v1.y);
    U.h2[3] = __floats2half2_rn(v1.z, v1.w);
    *reinterpret_cast<uint4*>(&g_A_hi[(size_t)row * IN_F + q * 8]) = U.u;
}

// ================= CSR build =================
__global__ void k_zero_counts() {
    int i = blockIdx.x * blockDim.x + threadIdx.x;
    if (i < N_NODES) g_cursor[i] = 0;
}
__global__ void k_hist(const int* __restrict__ edge_row) {
    int e = blockIdx.x * blockDim.x + threadIdx.x;
    if (e < N_EDGES) atomicAdd(&g_cursor[edge_row[e]], 1);
}
__global__ void k_scan1() {
    __shared__ int s[1024];
    int i = blockIdx.x * 1024 + threadIdx.x;
    int v = (i < N_NODES) ? g_cursor[i] : 0;
    s[threadIdx.x] = v;
    __syncthreads();
    #pragma unroll
    for (int d = 1; d < 1024; d <<= 1) {
        int t = (threadIdx.x >= (unsigned)d) ? s[threadIdx.x - d] : 0;
        __syncthreads();
        s[threadIdx.x] += t;
        __syncthreads();
    }
    if (i < N_NODES) g_row_ptr[i] = s[threadIdx.x] - v;   // block-local exclusive
    if (threadIdx.x == 1023) g_blk_sums[blockIdx.x] = s[1023];
}
// scan of 98 block sums, redundant per block in smem, then applied
__global__ void k_scan23() {
    __shared__ int s[128];
    if (threadIdx.x < 128) {
        int v = (threadIdx.x < 98) ? g_blk_sums[threadIdx.x] : 0;
        s[threadIdx.x] = v;
        __syncthreads();
        #pragma unroll
        for (int d = 1; d < 128; d <<= 1) {
            int t = (threadIdx.x >= (unsigned)d) ? s[threadIdx.x - d] : 0;
            __syncthreads();
            s[threadIdx.x] += t;
            __syncthreads();
        }
    } else {
        __syncthreads();
        #pragma unroll
        for (int d = 1; d < 128; d <<= 1) { __syncthreads(); __syncthreads(); }
    }
    __syncthreads();
    int i = blockIdx.x * blockDim.x + threadIdx.x;
    if (i < N_NODES) {
        int blk = i >> 10;
        int base = (blk == 0) ? 0 : s[blk - 1];     // exclusive
        int e = g_row_ptr[i] + base;
        g_row_ptr[i] = e;
        g_cursor[i]  = e;
    }
    if (i == 0) g_row_ptr[N_NODES] = s[97];
}
__global__ void k_scatter(const int* __restrict__ edge_row,
                          const int* __restrict__ edge_col,
                          const float* __restrict__ edge_val) {
    int e = blockIdx.x * blockDim.x + threadIdx.x;
    if (e < N_EDGES) {
        int r = edge_row[e];
        int p = atomicAdd(&g_cursor[r], 1);
        unsigned long long pk =
            ((unsigned long long)__float_as_uint(edge_val[e]) << 32)
            | (unsigned)edge_col[e];
        g_edge_sorted[p] = pk;
    }
}

// ================= HMMA GEMM: support = A @ W, fp32 accum =================
// BM=128, BN=128, BK=32, 256 threads (8 warps: 2 m-halves x 4 n-strips).
// 3-stage cp.async pipeline, one __syncthreads per K-chunk.
// smem rows: 32 data + 8 pad fp16 = 80B stride -> conflict-free ldmatrix.
__device__ __forceinline__ void ldmatrix_x4(uint32_t* r, uint32_t addr) {
    asm volatile("ldmatrix.sync.aligned.m8n8.x4.shared.b16 {%0,%1,%2,%3}, [%4];"
                 : "=r"(r[0]), "=r"(r[1]), "=r"(r[2]), "=r"(r[3]) : "r"(addr));
}
__device__ __forceinline__ void ldmatrix_x2(uint32_t* r, uint32_t addr) {
    asm volatile("ldmatrix.sync.aligned.m8n8.x2.shared.b16 {%0,%1}, [%2];"
                 : "=r"(r[0]), "=r"(r[1]) : "r"(addr));
}
__device__ __forceinline__ void mma16816(float* d, const uint32_t* a, const uint32_t* b) {
    asm volatile(
        "mma.sync.aligned.m16n8k16.row.col.f32.f16.f16.f32 "
        "{%0,%1,%2,%3}, {%4,%5,%6,%7}, {%8,%9}, {%0,%1,%2,%3};"
        : "+f"(d[0]), "+f"(d[1]), "+f"(d[2]), "+f"(d[3])
        : "r"(a[0]), "r"(a[1]), "r"(a[2]), "r"(a[3]), "r"(b[0]), "r"(b[1]));
}
__device__ __forceinline__ void cp_async16(uint32_t smem_addr, const void* gptr) {
    asm volatile("cp.async.cg.shared.global [%0], [%1], 16;"
                 :: "r"(smem_addr), "l"(gptr));
}
__device__ __forceinline__ void cp_commit() {
    asm volatile("cp.async.commit_group;");
}
template <int N>
__device__ __forceinline__ void cp_wait() {
    asm volatile("cp.async.wait_group %0;" :: "n"(N));
}
__device__ __forceinline__ uint32_t smem_u32(const void* p) {
    uint32_t a;
    asm("{ .reg .u64 t; cvta.to.shared.u64 t, %1; cvt.u32.u64 %0, t; }"
        : "=r"(a) : "l"(p));
    return a;
}

__global__ __launch_bounds__(256, 2) void k_gemm_mma(int ntile_base) {
    extern __shared__ __align__(16) char smem[];

    const int tid  = threadIdx.x;
    const int wid  = tid >> 5;
    const int lane = tid & 31;
    const int wm   = wid & 1;          // 0..1 (64 rows each)
    const int wn   = wid >> 1;         // 0..3 (32 cols each)
    const int mtile = blockIdx.y;
    const int ntile = ntile_base + blockIdx.x;

    const __half* A_h = g_A_hi + (size_t)mtile * 128 * IN_F;
    const __half* B_t = g_Wt   + (size_t)ntile * 128 * IN_F;

    const uint32_t sbase = smem_u32(smem);

    float acc[4][4][4];
    #pragma unroll
    for (int i = 0; i < 4; i++)
        #pragma unroll
        for (int j = 0; j < 4; j++)
            #pragma unroll
            for (int k = 0; k < 4; k++) acc[i][j][k] = 0.f;

    const int a_r  = lane & 15;
    const int a_hi = (lane >> 4) * 16;     // byte offset within 16-half k-step
    const int b_r  = lane & 7;
    const int b_hi = ((lane >> 3) & 1) * 16;

    auto load_stage = [&](int c, int s) {
        const int k0 = c * BK;
        const uint32_t st = sbase + s * STAGE_B;
        #pragma unroll
        for (int it = 0; it < 2; it++) {
            int idx = it * 256 + tid;
            int row = idx >> 2, q = idx & 3;
            uint32_t so = (uint32_t)row * (ROW_H * 2) + q * 16;
            const __half* ga = A_h + (size_t)row * IN_F + k0 + q * 8;
            const __half* gb = B_t + (size_t)row * IN_F + k0 + q * 8;
            cp_async16(st + so,          ga);
            cp_async16(st + TILE_B + so, gb);
        }
        cp_commit();
    };

    load_stage(0, 0);
    load_stage(1, 1);

    for (int c = 0; c < N_CHUNK; c++) {
        if (c == N_CHUNK - 1) cp_wait<0>(); else cp_wait<1>();
        __syncthreads();

        const int s = c % N_STAGE;
        const uint32_t st  = sbase + s * STAGE_B;
        const uint32_t sAH = st;
        const uint32_t sWT = st + TILE_B;

        #pragma unroll
        for (int ks = 0; ks < 2; ks++) {
            uint32_t bfrag[4][2];
            #pragma unroll
            for (int nt = 0; nt < 4; nt++) {
                uint32_t addr = sWT + (uint32_t)(wn * 32 + nt * 8 + b_r) * (ROW_H * 2)
                                + ks * 32 + b_hi;
                ldmatrix_x2(bfrag[nt], addr);
            }
            #pragma unroll
            for (int mt = 0; mt < 4; mt++) {
                uint32_t a[4];
                uint32_t addr = sAH + (uint32_t)(wm * 64 + mt * 16 + a_r) * (ROW_H * 2)
                                + ks * 32 + a_hi;
                ldmatrix_x4(a, addr);
                #pragma unroll
                for (int nt = 0; nt < 4; nt++) mma16816(acc[mt][nt], a, bfrag[nt]);
            }
        }

        if (c + 2 < N_CHUNK) load_stage(c + 2, (c + 2) % N_STAGE);
    }

    // epilogue: fp32 accum -> fp16 support
    const int mbase = mtile * 128 + wm * 64;
    const int nbase = ntile * 128 + wn * 32;
    #pragma unroll
    for (int mt = 0; mt < 4; mt++) {
        int r0 = mbase + mt * 16 + (lane >> 2);
        int col = nbase + 2 * (lane & 3);
        #pragma unroll
        for (int nt = 0; nt < 4; nt++) {
            int cc = col + nt * 8;
            if (r0 < N_NODES) {
                __half2 h = __floats2half2_rn(acc[mt][nt][0], acc[mt][nt][1]);
                *reinterpret_cast<__half2*>(&g_support[(size_t)r0 * OUT_F + cc]) = h;
            }
            if (r0 + 8 < N_NODES) {
                __half2 h = __floats2half2_rn(acc[mt][nt][2], acc[mt][nt][3]);
                *reinterpret_cast<__half2*>(&g_support[(size_t)(r0 + 8) * OUT_F + cc]) = h;
            }
        }
    }
}

// ================= CSR SpMM half (256 cols) + ReLU =================
// one warp per row (32 threads x 8 cols = 256 cols), 8 rows per 256-thread block
__global__ __launch_bounds__(256) void k_spmm_half(float* __restrict__ out,
                                                   int col_base) {
    const int r = blockIdx.x * 8 + (threadIdx.x >> 5);
    const int t = threadIdx.x & 31;
    if (r >= N_NODES) return;

    const int start = g_row_ptr[r];
    const int end   = g_row_ptr[r + 1];
    const int cb    = col_base + t * 8;

    float acc[8];
    #pragma unroll
    for (int j = 0; j < 8; j++) acc[j] = 0.f;

    #pragma unroll 8
    for (int i = start; i < end; i++) {
        unsigned long long pk = __ldg(&g_edge_sorted[i]);
        int   c = (int)(unsigned)pk;
        float v = __uint_as_float((unsigned)(pk >> 32));
        uint4 u = *reinterpret_cast<const uint4*>(
            &g_support[(size_t)c * OUT_F + cb]);
        const __half2* h = reinterpret_cast<const __half2*>(&u);
        #pragma unroll
        for (int j = 0; j < 4; j++) {
            float2 f = __half22float2(h[j]);
            acc[2 * j]     = fmaf(v, f.x, acc[2 * j]);
            acc[2 * j + 1] = fmaf(v, f.y, acc[2 * j + 1]);
        }
    }

    float* dst = &out[(size_t)r * OUT_F + cb];
    float4 o0 = make_float4(fmaxf(acc[0], 0.f), fmaxf(acc[1], 0.f),
                            fmaxf(acc[2], 0.f), fmaxf(acc[3], 0.f));
    float4 o1 = make_float4(fmaxf(acc[4], 0.f), fmaxf(acc[5], 0.f),
                            fmaxf(acc[6], 0.f), fmaxf(acc[7], 0.f));
    *reinterpret_cast<float4*>(dst)     = o0;
    *reinterpret_cast<float4*>(dst + 4) = o1;
}

// ================= launch =================
// R10 topology (proven best) with prep_W moved to the side-stream head:
// side: prep_W -> CSR chain -> (after G0) SpMM half 0.
// main: split_A -> wait(prep_W) -> G0 -> G1 -> SpMM half 1 -> join.
extern "C" void kernel_launch(void* const* d_in, const int* in_sizes, int n_in,
                              void* d_out, int out_size) {
    const float* features = (const float*)d_in[0];
    const float* weight   = (const float*)d_in[1];
    const int*   edge_row = (const int*)d_in[2];
    const int*   edge_col = (const int*)d_in[3];
    const float* edge_val = (const float*)d_in[4];
    float*       out      = (float*)d_out;

    // fork
    cudaEventRecord(g_ctx.e_fork, 0);
    cudaStreamWaitEvent(g_ctx.side, g_ctx.e_fork, 0);

    // ---- side stream: W prep, then CSR build ----
    k_prep_W<<<(OUT_F * IN_F) / 256, 256, 0, g_ctx.side>>>(weight);
    cudaEventRecord(g_ctx.e_w, g_ctx.side);
    k_zero_counts<<<(N_NODES + 255) / 256, 256, 0, g_ctx.side>>>();
    k_hist<<<(N_EDGES + 255) / 256, 256, 0, g_ctx.side>>>(edge_row);
    k_scan1<<<98, 1024, 0, g_ctx.side>>>();
    k_scan23<<<(N_NODES + 255) / 256, 256, 0, g_ctx.side>>>();
    k_scatter<<<(N_EDGES + 255) / 256, 256, 0, g_ctx.side>>>(edge_row, edge_col,
                                                             edge_val);

    // ---- main stream: A fp16 conversion, then GEMM half 0 (cols 0-255) ----
    {
        long long total = (long long)M_PAD * IN_F / 8;
        k_split_A<<<(unsigned)((total + 255) / 256), 256>>>(features);
    }
    cudaStreamWaitEvent(0, g_ctx.e_w, 0);
    k_gemm_mma<<<dim3(2, M_PAD / 128), 256, SMEM_TOT>>>(0);
    cudaEventRecord(g_ctx.e_g0, 0);

    // ---- side stream: SpMM half 0 (after its CSR chain + GEMM half 0) ----
    cudaStreamWaitEvent(g_ctx.side, g_ctx.e_g0, 0);
    k_spmm_half<<<(N_NODES + 7) / 8, 256, 0, g_ctx.side>>>(out, 0);
    cudaEventRecord(g_ctx.e_s0, g_ctx.side);

    // ---- main stream: GEMM half 1 (cols 256-511), then SpMM half 1 ----
    k_gemm_mma<<<dim3(2, M_PAD / 128), 256, SMEM_TOT>>>(2);
    k_spmm_half<<<(N_NODES + 7) / 8, 256>>>(out, 256);

    // join side stream into the capture (terminal merge)
    cudaStreamWaitEvent(0, g_ctx.e_s0, 0);
}

// round 15
// speedup vs baseline: 1.1256x; 1.0077x over previous
#include <cuda_runtime.h>
#include <cuda_fp16.h>
#include <stdint.h>

#define N_NODES 100000
#define IN_F    512
#define OUT_F   512
#define N_EDGES 3200000
#define M_PAD   100096   // 782 * 128

// ================= device scratch (no runtime allocation) =================
__device__ __half g_support[(size_t)M_PAD * OUT_F];   // fp16 support
__device__ __half g_A_hi[(size_t)M_PAD * IN_F];       // fp16 features
__device__ __half g_Wt[(size_t)OUT_F * IN_F];         // [n][k] = W[k][n], fp16
__device__ int   g_row_ptr[N_NODES + 1];
__device__ int   g_cursor[N_NODES];
__device__ unsigned long long g_edge_sorted[N_EDGES]; // (val_bits<<32)|col
__device__ int   g_blk_sums[128];

// ================= HMMA GEMM decls needed by ctor =================
#define BK        32
#define ROW_H     40                      // halves per smem row (80 B)
#define TILE_B    (128 * ROW_H * 2)       // 10240 B per tile
#define STAGE_B   (2 * TILE_B)            // A + W = 20480 B
#define N_STAGE   3
#define SMEM_TOT  (N_STAGE * STAGE_B)     // 61440 B
#define N_CHUNK   (IN_F / BK)             // 16

__global__ void k_gemm_mma(int ntile_base);

// ===== streams/events for fork-join inside graph capture (created once,
// before harness memory checkpoints; not device-memory allocation) =====
namespace {
struct Ctx {
    cudaStream_t side;
    cudaEvent_t  e_fork, e_w, e_g0, e_s0;
    Ctx() {
        cudaStreamCreateWithFlags(&side, cudaStreamNonBlocking);
        cudaEventCreateWithFlags(&e_fork, cudaEventDisableTiming);
        cudaEventCreateWithFlags(&e_w,    cudaEventDisableTiming);
        cudaEventCreateWithFlags(&e_g0,   cudaEventDisableTiming);
        cudaEventCreateWithFlags(&e_s0,   cudaEventDisableTiming);
        cudaFuncSetAttribute(k_gemm_mma,
                             cudaFuncAttributeMaxDynamicSharedMemorySize, SMEM_TOT);
    }
};
Ctx g_ctx;
}

// ================= prep: W transpose->fp16 + zero counts (fused) =================
__global__ void k_prep_W(const float* __restrict__ weight) {
    int i = blockIdx.x * blockDim.x + threadIdx.x;   // 0..262143
    int n = i >> 9, k = i & 511;
    g_Wt[i] = __float2half_rn(weight[(size_t)k * OUT_F + n]);
    if (i < N_NODES) g_cursor[i] = 0;
}
// features -> fp16, 8 floats per thread, one uint4 store
__global__ void k_split_A(const float* __restrict__ features) {
    long long t = (long long)blockIdx.x * blockDim.x + threadIdx.x;
    const long long total = (long long)M_PAD * IN_F / 8;   // 6406144
    if (t >= total) return;
    int row = (int)(t >> 6);          // 64 groups of 8 per row
    int q   = (int)(t & 63);
    float4 v0 = make_float4(0.f, 0.f, 0.f, 0.f);
    float4 v1 = make_float4(0.f, 0.f, 0.f, 0.f);
    if (row < N_NODES) {
        const float* p = &features[(size_t)row * IN_F + q * 8];
        v0 = *reinterpret_cast<const float4*>(p);
        v1 = *reinterpret_cast<const float4*>(p + 4);
    }
    union { uint4 u; __half2 h2[4]; } U;
    U.h2[0] = __floats2half2_rn(v0.x, v0.y);
    U.h2[1] = __floats2half2_rn(v0.z, v0.w);
    U.h2[2] = __floats2half2_rn(v1.x, v1.y);
    U.h2[3] = __floats2half2_rn(v1.z, v1.w);
    *reinterpret_cast<uint4*>(&g_A_hi[(size_t)row * IN_F + q * 8]) = U.u;
}

// ================= CSR build =================
__global__ void k_hist(const int* __restrict__ edge_row) {
    int e = blockIdx.x * blockDim.x + threadIdx.x;
    if (e < N_EDGES) atomicAdd(&g_cursor[edge_row[e]], 1);
}
__global__ void k_scan1() {
    __shared__ int s[1024];
    int i = blockIdx.x * 1024 + threadIdx.x;
    int v = (i < N_NODES) ? g_cursor[i] : 0;
    s[threadIdx.x] = v;
    __syncthreads();
    #pragma unroll
    for (int d = 1; d < 1024; d <<= 1) {
        int t = (threadIdx.x >= (unsigned)d) ? s[threadIdx.x - d] : 0;
        __syncthreads();
        s[threadIdx.x] += t;
        __syncthreads();
    }
    if (i < N_NODES) g_row_ptr[i] = s[threadIdx.x] - v;   // block-local exclusive
    if (threadIdx.x == 1023) g_blk_sums[blockIdx.x] = s[1023];
}
// scan of 98 block sums, redundant per block in smem, then applied
__global__ void k_scan23() {
    __shared__ int s[128];
    if (threadIdx.x < 128) {
        int v = (threadIdx.x < 98) ? g_blk_sums[threadIdx.x] : 0;
        s[threadIdx.x] = v;
        __syncthreads();
        #pragma unroll
        for (int d = 1; d < 128; d <<= 1) {
            int t = (threadIdx.x >= (unsigned)d) ? s[threadIdx.x - d] : 0;
            __syncthreads();
            s[threadIdx.x] += t;
            __syncthreads();
        }
    } else {
        __syncthreads();
        #pragma unroll
        for (int d = 1; d < 128; d <<= 1) { __syncthreads(); __syncthreads(); }
    }
    __syncthreads();
    int i = blockIdx.x * blockDim.x + threadIdx.x;
    if (i < N_NODES) {
        int blk = i >> 10;
        int base = (blk == 0) ? 0 : s[blk - 1];     // exclusive
        int e = g_row_ptr[i] + base;
        g_row_ptr[i] = e;
        g_cursor[i]  = e;
    }
    if (i == 0) g_row_ptr[N_NODES] = s[97];
}
__global__ void k_scatter(const int* __restrict__ edge_row,
                          const int* __restrict__ edge_col,
                          const float* __restrict__ edge_val) {
    int e = blockIdx.x * blockDim.x + threadIdx.x;
    if (e < N_EDGES) {
        int r = edge_row[e];
        int p = atomicAdd(&g_cursor[r], 1);
        unsigned long long pk =
            ((unsigned long long)__float_as_uint(edge_val[e]) << 32)
            | (unsigned)edge_col[e];
        g_edge_sorted[p] = pk;
    }
}

// ================= HMMA GEMM: support = A @ W, fp32 accum =================
// BM=128, BN=128, BK=32, 256 threads (8 warps: 2 m-halves x 4 n-strips).
// 3-stage cp.async pipeline, one __syncthreads per K-chunk.
// smem rows: 32 data + 8 pad fp16 = 80B stride -> conflict-free ldmatrix.
__device__ __forceinline__ void ldmatrix_x4(uint32_t* r, uint32_t addr) {
    asm volatile("ldmatrix.sync.aligned.m8n8.x4.shared.b16 {%0,%1,%2,%3}, [%4];"
                 : "=r"(r[0]), "=r"(r[1]), "=r"(r[2]), "=r"(r[3]) : "r"(addr));
}
__device__ __forceinline__ void ldmatrix_x2(uint32_t* r, uint32_t addr) {
    asm volatile("ldmatrix.sync.aligned.m8n8.x2.shared.b16 {%0,%1}, [%2];"
                 : "=r"(r[0]), "=r"(r[1]) : "r"(addr));
}
__device__ __forceinline__ void mma16816(float* d, const uint32_t* a, const uint32_t* b) {
    asm volatile(
        "mma.sync.aligned.m16n8k16.row.col.f32.f16.f16.f32 "
        "{%0,%1,%2,%3}, {%4,%5,%6,%7}, {%8,%9}, {%0,%1,%2,%3};"
        : "+f"(d[0]), "+f"(d[1]), "+f"(d[2]), "+f"(d[3])
        : "r"(a[0]), "r"(a[1]), "r"(a[2]), "r"(a[3]), "r"(b[0]), "r"(b[1]));
}
__device__ __forceinline__ void cp_async16(uint32_t smem_addr, const void* gptr) {
    asm volatile("cp.async.cg.shared.global [%0], [%1], 16;"
                 :: "r"(smem_addr), "l"(gptr));
}
__device__ __forceinline__ void cp_commit() {
    asm volatile("cp.async.commit_group;");
}
template <int N>
__device__ __forceinline__ void cp_wait() {
    asm volatile("cp.async.wait_group %0;" :: "n"(N));
}
__device__ __forceinline__ uint32_t smem_u32(const void* p) {
    uint32_t a;
    asm("{ .reg .u64 t; cvta.to.shared.u64 t, %1; cvt.u32.u64 %0, t; }"
        : "=r"(a) : "l"(p));
    return a;
}

__global__ __launch_bounds__(256, 2) void k_gemm_mma(int ntile_base) {
    extern __shared__ __align__(16) char smem[];

    const int tid  = threadIdx.x;
    const int wid  = tid >> 5;
    const int lane = tid & 31;
    const int wm   = wid & 1;          // 0..1 (64 rows each)
    const int wn   = wid >> 1;         // 0..3 (32 cols each)
    const int mtile = blockIdx.y;
    const int ntile = ntile_base + blockIdx.x;

    const __half* A_h = g_A_hi + (size_t)mtile * 128 * IN_F;
    const __half* B_t = g_Wt   + (size_t)ntile * 128 * IN_F;

    const uint32_t sbase = smem_u32(smem);

    float acc[4][4][4];
    #pragma unroll
    for (int i = 0; i < 4; i++)
        #pragma unroll
        for (int j = 0; j < 4; j++)
            #pragma unroll
            for (int k = 0; k < 4; k++) acc[i][j][k] = 0.f;

    const int a_r  = lane & 15;
    const int a_hi = (lane >> 4) * 16;     // byte offset within 16-half k-step
    const int b_r  = lane & 7;
    const int b_hi = ((lane >> 3) & 1) * 16;

    auto load_stage = [&](int c, int s) {
        const int k0 = c * BK;
        const uint32_t st = sbase + s * STAGE_B;
        #pragma unroll
        for (int it = 0; it < 2; it++) {
            int idx = it * 256 + tid;
            int row = idx >> 2, q = idx & 3;
            uint32_t so = (uint32_t)row * (ROW_H * 2) + q * 16;
            const __half* ga = A_h + (size_t)row * IN_F + k0 + q * 8;
            const __half* gb = B_t + (size_t)row * IN_F + k0 + q * 8;
            cp_async16(st + so,          ga);
            cp_async16(st + TILE_B + so, gb);
        }
        cp_commit();
    };

    load_stage(0, 0);
    load_stage(1, 1);

    for (int c = 0; c < N_CHUNK; c++) {
        if (c == N_CHUNK - 1) cp_wait<0>(); else cp_wait<1>();
        __syncthreads();

        const int s = c % N_STAGE;
        const uint32_t st  = sbase + s * STAGE_B;
        const uint32_t sAH = st;
        const uint32_t sWT = st + TILE_B;

        #pragma unroll
        for (int ks = 0; ks < 2; ks++) {
            uint32_t bfrag[4][2];
            #pragma unroll
            for (int nt = 0; nt < 4; nt++) {
                uint32_t addr = sWT + (uint32_t)(wn * 32 + nt * 8 + b_r) * (ROW_H * 2)
                                + ks * 32 + b_hi;
                ldmatrix_x2(bfrag[nt], addr);
            }
            #pragma unroll
            for (int mt = 0; mt < 4; mt++) {
                uint32_t a[4];
                uint32_t addr = sAH + (uint32_t)(wm * 64 + mt * 16 + a_r) * (ROW_H * 2)
                                + ks * 32 + a_hi;
                ldmatrix_x4(a, addr);
                #pragma unroll
                for (int nt = 0; nt < 4; nt++) mma16816(acc[mt][nt], a, bfrag[nt]);
            }
        }

        if (c + 2 < N_CHUNK) load_stage(c + 2, (c + 2) % N_STAGE);
    }

    // epilogue: fp32 accum -> fp16 support
    const int mbase = mtile * 128 + wm * 64;
    const int nbase = ntile * 128 + wn * 32;
    #pragma unroll
    for (int mt = 0; mt < 4; mt++) {
        int r0 = mbase + mt * 16 + (lane >> 2);
        int col = nbase + 2 * (lane & 3);
        #pragma unroll
        for (int nt = 0; nt < 4; nt++) {
            int cc = col + nt * 8;
            if (r0 < N_NODES) {
                __half2 h = __floats2half2_rn(acc[mt][nt][0], acc[mt][nt][1]);
                *reinterpret_cast<__half2*>(&g_support[(size_t)r0 * OUT_F + cc]) = h;
            }
            if (r0 + 8 < N_NODES) {
                __half2 h = __floats2half2_rn(acc[mt][nt][2], acc[mt][nt][3]);
                *reinterpret_cast<__half2*>(&g_support[(size_t)(r0 + 8) * OUT_F + cc]) = h;
            }
        }
    }
}

// ================= CSR SpMM half (256 cols) + ReLU =================
// one warp per row (32 threads x 8 cols = 256 cols), 4 rows per 128-thread block.
// Edge payload: __ldcs (streaming). Output: __stcs (streaming, write-once) so
// the 100MB of dead output writes don't evict the support set from L2.
__global__ __launch_bounds__(128) void k_spmm_half(float* __restrict__ out,
                                                   int col_base) {
    const int r = blockIdx.x * 4 + (threadIdx.x >> 5);
    const int t = threadIdx.x & 31;
    if (r >= N_NODES) return;

    const int start = g_row_ptr[r];
    const int end   = g_row_ptr[r + 1];
    const int cb    = col_base + t * 8;

    float acc[8];
    #pragma unroll
    for (int j = 0; j < 8; j++) acc[j] = 0.f;

    #pragma unroll 4
    for (int i = start; i < end; i++) {
        unsigned long long pk = __ldcs(&g_edge_sorted[i]);
        int   c = (int)(unsigned)pk;
        float v = __uint_as_float((unsigned)(pk >> 32));
        uint4 u = *reinterpret_cast<const uint4*>(
            &g_support[(size_t)c * OUT_F + cb]);
        const __half2* h = reinterpret_cast<const __half2*>(&u);
        #pragma unroll
        for (int j = 0; j < 4; j++) {
            float2 f = __half22float2(h[j]);
            acc[2 * j]     = fmaf(v, f.x, acc[2 * j]);
            acc[2 * j + 1] = fmaf(v, f.y, acc[2 * j + 1]);
        }
    }

    float* dst = &out[(size_t)r * OUT_F + cb];
    float4 o0 = make_float4(fmaxf(acc[0], 0.f), fmaxf(acc[1], 0.f),
                            fmaxf(acc[2], 0.f), fmaxf(acc[3], 0.f));
    float4 o1 = make_float4(fmaxf(acc[4], 0.f), fmaxf(acc[5], 0.f),
                            fmaxf(acc[6], 0.f), fmaxf(acc[7], 0.f));
    __stcs(reinterpret_cast<float4*>(dst),     o0);
    __stcs(reinterpret_cast<float4*>(dst + 4), o1);
}

// ================= launch =================
// R10 topology (proven best): side: prep_W(+zero) -> CSR -> (after G0) SpMM
// half 0. main: split_A -> wait(prep_W) -> G0 -> G1 -> SpMM half 1 -> join.
extern "C" void kernel_launch(void* const* d_in, const int* in_sizes, int n_in,
                              void* d_out, int out_size) {
    const float* features = (const float*)d_in[0];
    const float* weight   = (const float*)d_in[1];
    const int*   edge_row = (const int*)d_in[2];
    const int*   edge_col = (const int*)d_in[3];
    const float* edge_val = (const float*)d_in[4];
    float*       out      = (float*)d_out;

    // fork
    cudaEventRecord(g_ctx.e_fork, 0);
    cudaStreamWaitEvent(g_ctx.side, g_ctx.e_fork, 0);

    // ---- side stream: W prep (+ zero counts), then CSR build ----
    k_prep_W<<<(OUT_F * IN_F) / 256, 256, 0, g_ctx.side>>>(weight);
    cudaEventRecord(g_ctx.e_w, g_ctx.side);
    k_hist<<<(N_EDGES + 255) / 256, 256, 0, g_ctx.side>>>(edge_row);
    k_scan1<<<98, 1024, 0, g_ctx.side>>>();
    k_scan23<<<(N_NODES + 255) / 256, 256, 0, g_ctx.side>>>();
    k_scatter<<<(N_EDGES + 255) / 256, 256, 0, g_ctx.side>>>(edge_row, edge_col,
                                                             edge_val);

    // ---- main stream: A fp16 conversion, then GEMM half 0 (cols 0-255) ----
    {
        long long total = (long long)M_PAD * IN_F / 8;
        k_split_A<<<(unsigned)((total + 255) / 256), 256>>>(features);
    }
    cudaStreamWaitEvent(0, g_ctx.e_w, 0);
    k_gemm_mma<<<dim3(2, M_PAD / 128), 256, SMEM_TOT>>>(0);
    cudaEventRecord(g_ctx.e_g0, 0);

    // ---- side stream: SpMM half 0 (after its CSR chain + GEMM half 0) ----
    cudaStreamWaitEvent(g_ctx.side, g_ctx.e_g0, 0);
    k_spmm_half<<<N_NODES / 4, 128, 0, g_ctx.side>>>(out, 0);
    cudaEventRecord(g_ctx.e_s0, g_ctx.side);

    // ---- main stream: GEMM half 1 (cols 256-511), then SpMM half 1 ----
    k_gemm_mma<<<dim3(2, M_PAD / 128), 256, SMEM_TOT>>>(2);
    k_spmm_half<<<N_NODES / 4, 128>>>(out, 256);

    // join side stream into the capture (terminal merge)
    cudaStreamWaitEvent(0, g_ctx.e_s0, 0);
}

// round 16
// speedup vs baseline: 1.1498x; 1.0215x over previous
#include <cuda_runtime.h>
#include <cuda_fp16.h>
#include <stdint.h>

#define N_NODES 100000
#define IN_F    512
#define OUT_F   512
#define N_EDGES 3200000
#define M_PAD   100096   // 782 * 128
#define M_HALF  (M_PAD / 2)   // 50048 = 391 * 128

// ================= device scratch (no runtime allocation) =================
__device__ __half g_support[(size_t)M_PAD * OUT_F];   // fp16 support
__device__ __half g_A_hi[(size_t)M_PAD * IN_F];       // fp16 features
__device__ __half g_Wt[(size_t)OUT_F * IN_F];         // [n][k] = W[k][n], fp16
__device__ int   g_row_ptr[N_NODES + 1];
__device__ int   g_cursor[N_NODES];
__device__ unsigned long long g_edge_sorted[N_EDGES]; // (val_bits<<32)|col
__device__ int   g_blk_sums[128];

// ================= HMMA GEMM decls needed by ctor =================
#define BK        32
#define ROW_H     40                      // halves per smem row (80 B)
#define TILE_B    (128 * ROW_H * 2)       // 10240 B per tile
#define STAGE_B   (2 * TILE_B)            // A + W = 20480 B
#define N_STAGE   3
#define SMEM_TOT  (N_STAGE * STAGE_B)     // 61440 B
#define N_CHUNK   (IN_F / BK)             // 16

__global__ void k_gemm_mma(int ntile_base, int mtile_base);

// ===== streams/events for fork-join inside graph capture (created once,
// before harness memory checkpoints; not device-memory allocation) =====
namespace {
struct Ctx {
    cudaStream_t side, side2;
    cudaEvent_t  e_fork, e_w, e_ca0, e_ca1, e_g0, e_s0;
    Ctx() {
        cudaStreamCreateWithFlags(&side,  cudaStreamNonBlocking);
        cudaStreamCreateWithFlags(&side2, cudaStreamNonBlocking);
        cudaEventCreateWithFlags(&e_fork, cudaEventDisableTiming);
        cudaEventCreateWithFlags(&e_w,    cudaEventDisableTiming);
        cudaEventCreateWithFlags(&e_ca0,  cudaEventDisableTiming);
        cudaEventCreateWithFlags(&e_ca1,  cudaEventDisableTiming);
        cudaEventCreateWithFlags(&e_g0,   cudaEventDisableTiming);
        cudaEventCreateWithFlags(&e_s0,   cudaEventDisableTiming);
        cudaFuncSetAttribute(k_gemm_mma,
                             cudaFuncAttributeMaxDynamicSharedMemorySize, SMEM_TOT);
    }
};
Ctx g_ctx;
}

// ================= prep: W transpose->fp16 + zero counts (fused) =================
__global__ void k_prep_W(const float* __restrict__ weight) {
    int i = blockIdx.x * blockDim.x + threadIdx.x;   // 0..262143
    int n = i >> 9, k = i & 511;
    g_Wt[i] = __float2half_rn(weight[(size_t)k * OUT_F + n]);
    if (i < N_NODES) g_cursor[i] = 0;
}
// features -> fp16 for rows [row_base, row_base + M_HALF)
__global__ void k_split_A(const float* __restrict__ features, int row_base) {
    long long t = (long long)blockIdx.x * blockDim.x + threadIdx.x;
    const long long total = (long long)M_HALF * IN_F / 8;   // 3203072
    if (t >= total) return;
    int row = row_base + (int)(t >> 6);   // 64 groups of 8 per row
    int q   = (int)(t & 63);
    float4 v0 = make_float4(0.f, 0.f, 0.f, 0.f);
    float4 v1 = make_float4(0.f, 0.f, 0.f, 0.f);
    if (row < N_NODES) {
        const float* p = &features[(size_t)row * IN_F + q * 8];
        v0 = *reinterpret_cast<const float4*>(p);
        v1 = *reinterpret_cast<const float4*>(p + 4);
    }
    union { uint4 u; __half2 h2[4]; } U;
    U.h2[0] = __floats2half2_rn(v0.x, v0.y);
    U.h2[1] = __floats2half2_rn(v0.z, v0.w);
    U.h2[2] = __floats2half2_rn(v1.x, v1.y);
    U.h2[3] = __floats2half2_rn(v1.z, v1.w);
    *reinterpret_cast<uint4*>(&g_A_hi[(size_t)row * IN_F + q * 8]) = U.u;
}

// ================= CSR build =================
__global__ void k_hist(const int* __restrict__ edge_row) {
    int e = blockIdx.x * blockDim.x + threadIdx.x;
    if (e < N_EDGES) atomicAdd(&g_cursor[edge_row[e]], 1);
}
__global__ void k_scan1() {
    __shared__ int s[1024];
    int i = blockIdx.x * 1024 + threadIdx.x;
    int v = (i < N_NODES) ? g_cursor[i] : 0;
    s[threadIdx.x] = v;
    __syncthreads();
    #pragma unroll
    for (int d = 1; d < 1024; d <<= 1) {
        int t = (threadIdx.x >= (unsigned)d) ? s[threadIdx.x - d] : 0;
        __syncthreads();
        s[threadIdx.x] += t;
        __syncthreads();
    }
    if (i < N_NODES) g_row_ptr[i] = s[threadIdx.x] - v;   // block-local exclusive
    if (threadIdx.x == 1023) g_blk_sums[blockIdx.x] = s[1023];
}
// scan of 98 block sums, redundant per block in smem, then applied
__global__ void k_scan23() {
    __shared__ int s[128];
    if (threadIdx.x < 128) {
        int v = (threadIdx.x < 98) ? g_blk_sums[threadIdx.x] : 0;
        s[threadIdx.x] = v;
        __syncthreads();
        #pragma unroll
        for (int d = 1; d < 128; d <<= 1) {
            int t = (threadIdx.x >= (unsigned)d) ? s[threadIdx.x - d] : 0;
            __syncthreads();
            s[threadIdx.x] += t;
            __syncthreads();
        }
    } else {
        __syncthreads();
        #pragma unroll
        for (int d = 1; d < 128; d <<= 1) { __syncthreads(); __syncthreads(); }
    }
    __syncthreads();
    int i = blockIdx.x * blockDim.x + threadIdx.x;
    if (i < N_NODES) {
        int blk = i >> 10;
        int base = (blk == 0) ? 0 : s[blk - 1];     // exclusive
        int e = g_row_ptr[i] + base;
        g_row_ptr[i] = e;
        g_cursor[i]  = e;
    }
    if (i == 0) g_row_ptr[N_NODES] = s[97];
}
__global__ void k_scatter(const int* __restrict__ edge_row,
                          const int* __restrict__ edge_col,
                          const float* __restrict__ edge_val) {
    int e = blockIdx.x * blockDim.x + threadIdx.x;
    if (e < N_EDGES) {
        int r = edge_row[e];
        int p = atomicAdd(&g_cursor[r], 1);
        unsigned long long pk =
            ((unsigned long long)__float_as_uint(edge_val[e]) << 32)
            | (unsigned)edge_col[e];
        g_edge_sorted[p] = pk;
    }
}

// ================= HMMA GEMM: support = A @ W, fp32 accum =================
// BM=128, BN=128, BK=32, 256 threads (8 warps: 2 m-halves x 4 n-strips).
// 3-stage cp.async pipeline, one __syncthreads per K-chunk.
// smem rows: 32 data + 8 pad fp16 = 80B stride -> conflict-free ldmatrix.
__device__ __forceinline__ void ldmatrix_x4(uint32_t* r, uint32_t addr) {
    asm volatile("ldmatrix.sync.aligned.m8n8.x4.shared.b16 {%0,%1,%2,%3}, [%4];"
                 : "=r"(r[0]), "=r"(r[1]), "=r"(r[2]), "=r"(r[3]) : "r"(addr));
}
__device__ __forceinline__ void ldmatrix_x2(uint32_t* r, uint32_t addr) {
    asm volatile("ldmatrix.sync.aligned.m8n8.x2.shared.b16 {%0,%1}, [%2];"
                 : "=r"(r[0]), "=r"(r[1]) : "r"(addr));
}
__device__ __forceinline__ void mma16816(float* d, const uint32_t* a, const uint32_t* b) {
    asm volatile(
        "mma.sync.aligned.m16n8k16.row.col.f32.f16.f16.f32 "
        "{%0,%1,%2,%3}, {%4,%5,%6,%7}, {%8,%9}, {%0,%1,%2,%3};"
        : "+f"(d[0]), "+f"(d[1]), "+f"(d[2]), "+f"(d[3])
        : "r"(a[0]), "r"(a[1]), "r"(a[2]), "r"(a[3]), "r"(b[0]), "r"(b[1]));
}
__device__ __forceinline__ void cp_async16(uint32_t smem_addr, const void* gptr) {
    asm volatile("cp.async.cg.shared.global [%0], [%1], 16;"
                 :: "r"(smem_addr), "l"(gptr));
}
__device__ __forceinline__ void cp_commit() {
    asm volatile("cp.async.commit_group;");
}
template <int N>
__device__ __forceinline__ void cp_wait() {
    asm volatile("cp.async.wait_group %0;" :: "n"(N));
}
__device__ __forceinline__ uint32_t smem_u32(const void* p) {
    uint32_t a;
    asm("{ .reg .u64 t; cvta.to.shared.u64 t, %1; cvt.u32.u64 %0, t; }"
        : "=r"(a) : "l"(p));
    return a;
}

__global__ __launch_bounds__(256, 2) void k_gemm_mma(int ntile_base,
                                                     int mtile_base) {
    extern __shared__ __align__(16) char smem[];

    const int tid  = threadIdx.x;
    const int wid  = tid >> 5;
    const int lane = tid & 31;
    const int wm   = wid & 1;          // 0..1 (64 rows each)
    const int wn   = wid >> 1;         // 0..3 (32 cols each)
    const int mtile = mtile_base + blockIdx.y;
    const int ntile = ntile_base + blockIdx.x;

    const __half* A_h = g_A_hi + (size_t)mtile * 128 * IN_F;
    const __half* B_t = g_Wt   + (size_t)ntile * 128 * IN_F;

    const uint32_t sbase = smem_u32(smem);

    float acc[4][4][4];
    #pragma unroll
    for (int i = 0; i < 4; i++)
        #pragma unroll
        for (int j = 0; j < 4; j++)
            #pragma unroll
            for (int k = 0; k < 4; k++) acc[i][j][k] = 0.f;

    const int a_r  = lane & 15;
    const int a_hi = (lane >> 4) * 16;     // byte offset within 16-half k-step
    const int b_r  = lane & 7;
    const int b_hi = ((lane >> 3) & 1) * 16;

    auto load_stage = [&](int c, int s) {
        const int k0 = c * BK;
        const uint32_t st = sbase + s * STAGE_B;
        #pragma unroll
        for (int it = 0; it < 2; it++) {
            int idx = it * 256 + tid;
            int row = idx >> 2, q = idx & 3;
            uint32_t so = (uint32_t)row * (ROW_H * 2) + q * 16;
            const __half* ga = A_h + (size_t)row * IN_F + k0 + q * 8;
            const __half* gb = B_t + (size_t)row * IN_F + k0 + q * 8;
            cp_async16(st + so,          ga);
            cp_async16(st + TILE_B + so, gb);
        }
        cp_commit();
    };

    load_stage(0, 0);
    load_stage(1, 1);

    for (int c = 0; c < N_CHUNK; c++) {
        if (c == N_CHUNK - 1) cp_wait<0>(); else cp_wait<1>();
        __syncthreads();

        const int s = c % N_STAGE;
        const uint32_t st  = sbase + s * STAGE_B;
        const uint32_t sAH = st;
        const uint32_t sWT = st + TILE_B;

        #pragma unroll
        for (int ks = 0; ks < 2; ks++) {
            uint32_t bfrag[4][2];
            #pragma unroll
            for (int nt = 0; nt < 4; nt++) {
                uint32_t addr = sWT + (uint32_t)(wn * 32 + nt * 8 + b_r) * (ROW_H * 2)
                                + ks * 32 + b_hi;
                ldmatrix_x2(bfrag[nt], addr);
            }
            #pragma unroll
            for (int mt = 0; mt < 4; mt++) {
                uint32_t a[4];
                uint32_t addr = sAH + (uint32_t)(wm * 64 + mt * 16 + a_r) * (ROW_H * 2)
                                + ks * 32 + a_hi;
                ldmatrix_x4(a, addr);
                #pragma unroll
                for (int nt = 0; nt < 4; nt++) mma16816(acc[mt][nt], a, bfrag[nt]);
            }
        }

        if (c + 2 < N_CHUNK) load_stage(c + 2, (c + 2) % N_STAGE);
    }

    // epilogue: fp32 accum -> fp16 support
    const int mbase = mtile * 128 + wm * 64;
    const int nbase = ntile * 128 + wn * 32;
    #pragma unroll
    for (int mt = 0; mt < 4; mt++) {
        int r0 = mbase + mt * 16 + (lane >> 2);
        int col = nbase + 2 * (lane & 3);
        #pragma unroll
        for (int nt = 0; nt < 4; nt++) {
            int cc = col + nt * 8;
            if (r0 < N_NODES) {
                __half2 h = __floats2half2_rn(acc[mt][nt][0], acc[mt][nt][1]);
                *reinterpret_cast<__half2*>(&g_support[(size_t)r0 * OUT_F + cc]) = h;
            }
            if (r0 + 8 < N_NODES) {
                __half2 h = __floats2half2_rn(acc[mt][nt][2], acc[mt][nt][3]);
                *reinterpret_cast<__half2*>(&g_support[(size_t)(r0 + 8) * OUT_F + cc]) = h;
            }
        }
    }
}

// ================= CSR SpMM half (256 cols) + ReLU =================
// one warp per row (32 threads x 8 cols = 256 cols), 4 rows per 128-thread block.
// Edges consumed in 16B pairs (one __ldcs per 2 edges); odd head/tail peeled.
__global__ __launch_bounds__(128) void k_spmm_half(float* __restrict__ out,
                                                   int col_base) {
    const int r = blockIdx.x * 4 + (threadIdx.x >> 5);
    const int t = threadIdx.x & 31;
    if (r >= N_NODES) return;

    const int start = g_row_ptr[r];
    const int end   = g_row_ptr[r + 1];
    const int cb    = col_base + t * 8;

    float acc[8];
    #pragma unroll
    for (int j = 0; j < 8; j++) acc[j] = 0.f;

    auto do_edge = [&](unsigned col, unsigned valbits) {
        float v = __uint_as_float(valbits);
        uint4 u = *reinterpret_cast<const uint4*>(
            &g_support[(size_t)col * OUT_F + cb]);
        const __half2* h = reinterpret_cast<const __half2*>(&u);
        #pragma unroll
        for (int j = 0; j < 4; j++) {
            float2 f = __half22float2(h[j]);
            acc[2 * j]     = fmaf(v, f.x, acc[2 * j]);
            acc[2 * j + 1] = fmaf(v, f.y, acc[2 * j + 1]);
        }
    };

    int i = start;
    if (i < end && (i & 1)) {               // align to 16B pair boundary
        unsigned long long pk = __ldcs(&g_edge_sorted[i]);
        do_edge((unsigned)pk, (unsigned)(pk >> 32));
        i++;
    }
    #pragma unroll 2
    for (; i + 1 < end; i += 2) {
        uint4 e2 = __ldcs(reinterpret_cast<const uint4*>(&g_edge_sorted[i]));
        // little-endian u64: .x = col0, .y = val0, .z = col1, .w = val1
        do_edge(e2.x, e2.y);
        do_edge(e2.z, e2.w);
    }
    if (i < end) {
        unsigned long long pk = __ldcs(&g_edge_sorted[i]);
        do_edge((unsigned)pk, (unsigned)(pk >> 32));
    }

    float* dst = &out[(size_t)r * OUT_F + cb];
    float4 o0 = make_float4(fmaxf(acc[0], 0.f), fmaxf(acc[1], 0.f),
                            fmaxf(acc[2], 0.f), fmaxf(acc[3], 0.f));
    float4 o1 = make_float4(fmaxf(acc[4], 0.f), fmaxf(acc[5], 0.f),
                            fmaxf(acc[6], 0.f), fmaxf(acc[7], 0.f));
    __stcs(reinterpret_cast<float4*>(dst),     o0);
    __stcs(reinterpret_cast<float4*>(dst + 4), o1);
}

// ================= launch =================
// R10 topology + M-pipelined conversion under G0:
//   side : prep_W(+zero) -> CSR chain -> (after G0 complete) SpMM half 0.
//   side2: wait(convA half0) -> convA half1 -> e_ca1.
//   main : convA half0 -> wait(e_w) -> G0a (M-half0) -> wait(e_ca1) ->
//          G0b (M-half1) -> e_g0 -> G1 (full M) -> SpMM half 1 -> join e_s0.
extern "C" void kernel_launch(void* const* d_in, const int* in_sizes, int n_in,
                              void* d_out, int out_size) {
    const float* features = (const float*)d_in[0];
    const float* weight   = (const float*)d_in[1];
    const int*   edge_row = (const int*)d_in[2];
    const int*   edge_col = (const int*)d_in[3];
    const float* edge_val = (const float*)d_in[4];
    float*       out      = (float*)d_out;

    const unsigned convGrid = (unsigned)(((long long)M_HALF * IN_F / 8 + 255) / 256);

    // fork
    cudaEventRecord(g_ctx.e_fork, 0);
    cudaStreamWaitEvent(g_ctx.side,  g_ctx.e_fork, 0);
    cudaStreamWaitEvent(g_ctx.side2, g_ctx.e_fork, 0);

    // ---- side stream: W prep (+ zero counts), then CSR build ----
    k_prep_W<<<(OUT_F * IN_F) / 256, 256, 0, g_ctx.side>>>(weight);
    cudaEventRecord(g_ctx.e_w, g_ctx.side);
    k_hist<<<(N_EDGES + 255) / 256, 256, 0, g_ctx.side>>>(edge_row);
    k_scan1<<<98, 1024, 0, g_ctx.side>>>();
    k_scan23<<<(N_NODES + 255) / 256, 256, 0, g_ctx.side>>>();
    k_scatter<<<(N_EDGES + 255) / 256, 256, 0, g_ctx.side>>>(edge_row, edge_col,
                                                             edge_val);

    // ---- main: convert A rows [0, M_HALF) ----
    k_split_A<<<convGrid, 256>>>(features, 0);
    cudaEventRecord(g_ctx.e_ca0, 0);

    // ---- side2: convert A rows [M_HALF, M_PAD) while G0a runs ----
    cudaStreamWaitEvent(g_ctx.side2, g_ctx.e_ca0, 0);
    k_split_A<<<convGrid, 256, 0, g_ctx.side2>>>(features, M_HALF);
    cudaEventRecord(g_ctx.e_ca1, g_ctx.side2);

    // ---- main: G0a (cols 0-255, M rows 0..M_HALF) ----
    cudaStreamWaitEvent(0, g_ctx.e_w, 0);
    k_gemm_mma<<<dim3(2, M_HALF / 128), 256, SMEM_TOT>>>(0, 0);
    // ---- main: G0b (cols 0-255, M rows M_HALF..M_PAD) ----
    cudaStreamWaitEvent(0, g_ctx.e_ca1, 0);   // joins side2
    k_gemm_mma<<<dim3(2, M_HALF / 128), 256, SMEM_TOT>>>(0, M_HALF / 128);
    cudaEventRecord(g_ctx.e_g0, 0);

    // ---- side stream: SpMM half 0 (after its CSR chain + full G0) ----
    cudaStreamWaitEvent(g_ctx.side, g_ctx.e_g0, 0);
    k_spmm_half<<<N_NODES / 4, 128, 0, g_ctx.side>>>(out, 0);
    cudaEventRecord(g_ctx.e_s0, g_ctx.side);

    // ---- main: G1 (cols 256-511, full M), then SpMM half 1 ----
    k_gemm_mma<<<dim3(2, M_PAD / 128), 256, SMEM_TOT>>>(2, 0);
    k_spmm_half<<<N_NODES / 4, 128>>>(out, 256);

    // join side stream into the capture (terminal merge)
    cudaStreamWaitEvent(0, g_ctx.e_s0, 0);
}